// round 10
// baseline (speedup 1.0000x reference)
#include <cuda_runtime.h>
#include <cuda_bf16.h>
#include <cstdint>

// Problem constants
#define NB  16
#define NN  1024
#define FIN 64
#define HH  256
#define NEGV  (-9e15f)
#define ALPHA 0.2f

typedef __nv_bfloat16 bf16;

// ---------------- scratch (device globals; no allocation allowed) ----------------
__device__ bf16 g_nfhi[NB * NN * FIN], g_nflo[NB * NN * FIN];       // 2MB each
__device__ bf16 g_eWhi[FIN * HH],      g_eWlo[FIN * HH];
__device__ bf16 g_W0hi[HH * HH],       g_W0lo[HH * HH];
__device__ bf16 g_W1hi[HH * HH],       g_W1lo[HH * HH];
__device__ bf16 g_xhi [NB * NN * HH],  g_xlo [NB * NN * HH];        // 8MB each
__device__ bf16 g_hhi [NB * NN * HH],  g_hlo [NB * NN * HH];
__device__ bf16 g_yhi [NB * NN * HH],  g_ylo [NB * NN * HH];
__device__ bf16 g_atthi[(size_t)NB * NN * NN], g_attlo[(size_t)NB * NN * NN]; // 33.5MB each
__device__ float g_s1 [NB * NN];
__device__ float g_s2 [NB * NN];
__device__ float g_ps [NB * 8 * HH];
__device__ float g_pm [NB * 8 * HH];

// ---------------- helpers ----------------
__device__ __forceinline__ uint32_t smem_u32(const void* p) {
    uint32_t a;
    asm("{ .reg .u64 t; cvta.to.shared.u64 t, %1; cvt.u32.u64 %0, t; }" : "=r"(a) : "l"(p));
    return a;
}
__device__ __forceinline__ void split_pair(float x, float y, uint32_t& hi, uint32_t& lo) {
    __nv_bfloat162 h = __floats2bfloat162_rn(x, y);
    float rx = x - __bfloat162float(__low2bfloat16(h));
    float ry = y - __bfloat162float(__high2bfloat16(h));
    __nv_bfloat162 l = __floats2bfloat162_rn(rx, ry);
    hi = *(uint32_t*)&h;
    lo = *(uint32_t*)&l;
}

#define CP16(dst, src) \
    asm volatile("cp.async.cg.shared.global [%0], [%1], 16;" :: "r"(dst), "l"(src))
#define CP_COMMIT() asm volatile("cp.async.commit_group;")
#define CP_WAIT(n)  asm volatile("cp.async.wait_group %0;" :: "n"(n))

#define LDSM_X4(r0, r1, r2, r3, addr) \
    asm volatile("ldmatrix.sync.aligned.m8n8.x4.shared.b16 {%0,%1,%2,%3}, [%4];" \
                 : "=r"(r0), "=r"(r1), "=r"(r2), "=r"(r3) : "r"(addr))
#define LDSM_X4T(r0, r1, r2, r3, addr) \
    asm volatile("ldmatrix.sync.aligned.m8n8.x4.trans.shared.b16 {%0,%1,%2,%3}, [%4];" \
                 : "=r"(r0), "=r"(r1), "=r"(r2), "=r"(r3) : "r"(addr))
#define MMA16816(d, a, b) \
    asm volatile("mma.sync.aligned.m16n8k16.row.col.f32.bf16.bf16.f32 " \
                 "{%0,%1,%2,%3}, {%4,%5,%6,%7}, {%8,%9}, {%0,%1,%2,%3};" \
                 : "+f"(d[0]), "+f"(d[1]), "+f"(d[2]), "+f"(d[3]) \
                 : "r"(a[0]), "r"(a[1]), "r"(a[2]), "r"(a[3]), "r"(b[0]), "r"(b[1]))

// ---------------- warp reductions ----------------
__device__ __forceinline__ float warpMax(float v) {
    #pragma unroll
    for (int o = 16; o > 0; o >>= 1) v = fmaxf(v, __shfl_xor_sync(0xFFFFFFFFu, v, o));
    return v;
}
__device__ __forceinline__ float warpSum(float v) {
    #pragma unroll
    for (int o = 16; o > 0; o >>= 1) v += __shfl_xor_sync(0xFFFFFFFFu, v, o);
    return v;
}

// ============================================================================
// Pre-split bf16 GEMM via mma.sync, fp32 accum, cp.async double-buffered.
// C[M,Nn] = (Ahi+Alo)[M,K] @ (Bhi+Blo)[K,Nn] (+bias)(relu)
// Output either fp32 C or split bf16 (Chi,Clo). Block 128x128, BK=32,
// 256 threads (8 warps, 64x32 warp tiles). A smem [m][k] pad 40 elems;
// B smem [k][n] pad 136 elems (ldmatrix.trans). Batched via blockIdx.z.
// ============================================================================
#define APAD 40
#define BPAD 136
// stage layout (bytes): Ah 10240 | Al 10240 | Bh 8704 | Bl 8704  = 37888
#define AL_OFF 10240
#define BH_OFF 20480
#define BL_OFF 29184
#define STAGE  37888
static constexpr int GSMEM = 2 * STAGE;

template<bool BIAS, bool RELU, bool SPLITOUT>
__global__ __launch_bounds__(256)
void bgemm(const bf16* __restrict__ Ahi, const bf16* __restrict__ Alo,
           const bf16* __restrict__ Bhi, const bf16* __restrict__ Blo,
           const float* __restrict__ bias,
           float* __restrict__ Cf, bf16* __restrict__ Chi, bf16* __restrict__ Clo,
           int M, int K, int Nn,
           long long sA, long long sB, long long sC)
{
    constexpr int BK = 32;
    extern __shared__ char dsm[];
    const uint32_t sb = smem_u32(dsm);

    const long long zA = (long long)blockIdx.z * sA;
    const long long zB = (long long)blockIdx.z * sB;
    const long long zC = (long long)blockIdx.z * sC;
    const bf16* pAh = Ahi + zA;
    const bf16* pAl = Alo + zA;
    const bf16* pBh = Bhi + zB;
    const bf16* pBl = Blo + zB;

    const int bm = blockIdx.y * 128;
    const int bn = blockIdx.x * 128;
    const int tid  = threadIdx.x;
    const int lane = tid & 31;
    const int wid  = tid >> 5;
    const int m0 = (wid & 1) * 64, n0 = (wid >> 1) * 32;

    // per-thread fill indices
    const int ar = (tid << 1) >> 3;           // rows for 2 A tasks: t, t+256
    // (computed inline below instead)

    // per-thread ldmatrix base offsets (bytes, within a stage)
    const uint32_t aoff = (uint32_t)(((m0 + (lane & 7) + ((lane >> 3) & 1) * 8) * APAD
                                     + (lane >> 4) * 8) * 2);
    const uint32_t boff = (uint32_t)((((lane & 7) + ((lane >> 3) & 1) * 8) * BPAD
                                     + n0 + (lane >> 4) * 8) * 2);

    float acc[4][4][4];
    #pragma unroll
    for (int mi = 0; mi < 4; mi++)
        #pragma unroll
        for (int ni = 0; ni < 4; ni++)
            #pragma unroll
            for (int r = 0; r < 4; r++) acc[mi][ni][r] = 0.f;

    const int nIter = K / BK;

    // ---- async fill of one stage ----
    auto fill = [&](int stage, int k0) {
        uint32_t base = sb + stage * STAGE;
        #pragma unroll
        for (int l = 0; l < 2; l++) {
            int t = tid + (l << 8);           // 0..511
            int row = t >> 2, seg = t & 3;
            long long gsrc = (long long)(bm + row) * K + k0 + seg * 8;
            uint32_t d = base + row * 80 + seg * 16;
            CP16(d,          pAh + gsrc);
            CP16(d + AL_OFF, pAl + gsrc);
        }
        #pragma unroll
        for (int l = 0; l < 2; l++) {
            int t = tid + (l << 8);           // 0..511
            int row = t >> 4, seg = t & 15;
            long long gsrc = (long long)(k0 + row) * Nn + bn + seg * 8;
            uint32_t d = base + BH_OFF + row * 272 + seg * 16;
            CP16(d,                    pBh + gsrc);
            CP16(d + (BL_OFF - BH_OFF), pBl + gsrc);
        }
        CP_COMMIT();
    };

    fill(0, 0);

    for (int c = 0; c < nIter; ++c) {
        if (c + 1 < nIter) {
            fill((c + 1) & 1, (c + 1) * BK);
            CP_WAIT(1);
        } else {
            CP_WAIT(0);
        }
        __syncthreads();

        const uint32_t base = sb + (c & 1) * STAGE;
        const uint32_t aHi = base,           aLo = base + AL_OFF;
        const uint32_t bHi = base + BH_OFF,  bLo = base + BL_OFF;

        #pragma unroll
        for (int kk = 0; kk < BK; kk += 16) {
            uint32_t ah[4][4], al[4][4], bh[4][2], bl[4][2];
            #pragma unroll
            for (int mi = 0; mi < 4; mi++) {
                uint32_t d = (uint32_t)((mi * 16 * APAD + kk) * 2);
                LDSM_X4(ah[mi][0], ah[mi][1], ah[mi][2], ah[mi][3], aHi + aoff + d);
                LDSM_X4(al[mi][0], al[mi][1], al[mi][2], al[mi][3], aLo + aoff + d);
            }
            #pragma unroll
            for (int p = 0; p < 2; p++) {
                uint32_t d = (uint32_t)((kk * BPAD + p * 16) * 2);
                LDSM_X4T(bh[2 * p][0], bh[2 * p][1], bh[2 * p + 1][0], bh[2 * p + 1][1],
                         bHi + boff + d);
                LDSM_X4T(bl[2 * p][0], bl[2 * p][1], bl[2 * p + 1][0], bl[2 * p + 1][1],
                         bLo + boff + d);
            }
            #pragma unroll
            for (int mi = 0; mi < 4; mi++)
                #pragma unroll
                for (int ni = 0; ni < 4; ni++) {
                    MMA16816(acc[mi][ni], ah[mi], bh[ni]);
                    MMA16816(acc[mi][ni], ah[mi], bl[ni]);
                    MMA16816(acc[mi][ni], al[mi], bh[ni]);
                }
        }
        __syncthreads();
    }

    // ---- epilogue ----
    const int rbase = bm + m0 + (lane >> 2);
    const int cbase = bn + n0 + 2 * (lane & 3);
    #pragma unroll
    for (int ni = 0; ni < 4; ni++) {
        int col = cbase + ni * 8;
        float2 bb = make_float2(0.f, 0.f);
        if (BIAS) bb = *(const float2*)(bias + col);
        #pragma unroll
        for (int mi = 0; mi < 4; mi++) {
            int r0 = rbase + mi * 16;
            float2 v0 = make_float2(acc[mi][ni][0] + bb.x, acc[mi][ni][1] + bb.y);
            float2 v1 = make_float2(acc[mi][ni][2] + bb.x, acc[mi][ni][3] + bb.y);
            if (RELU) {
                v0.x = fmaxf(v0.x, 0.f); v0.y = fmaxf(v0.y, 0.f);
                v1.x = fmaxf(v1.x, 0.f); v1.y = fmaxf(v1.y, 0.f);
            }
            if (SPLITOUT) {
                uint32_t h0, l0, h1, l1;
                split_pair(v0.x, v0.y, h0, l0);
                split_pair(v1.x, v1.y, h1, l1);
                *(uint32_t*)(Chi + zC + (long long)r0 * Nn + col)       = h0;
                *(uint32_t*)(Clo + zC + (long long)r0 * Nn + col)       = l0;
                *(uint32_t*)(Chi + zC + (long long)(r0 + 8) * Nn + col) = h1;
                *(uint32_t*)(Clo + zC + (long long)(r0 + 8) * Nn + col) = l1;
            } else {
                *(float2*)(Cf + zC + (long long)r0 * Nn + col)       = v0;
                *(float2*)(Cf + zC + (long long)(r0 + 8) * Nn + col) = v1;
            }
        }
    }
    (void)ar;
}

// ---------------- prep: split fp32 array into bf16 hi/lo ----------------
__global__ __launch_bounds__(256)
void split_prep(const float* __restrict__ src, bf16* __restrict__ hi,
                bf16* __restrict__ lo, int n4)
{
    int i = blockIdx.x * blockDim.x + threadIdx.x;
    if (i < n4) {
        float4 v = ((const float4*)src)[i];
        uint32_t h0, l0, h1, l1;
        split_pair(v.x, v.y, h0, l0);
        split_pair(v.z, v.w, h1, l1);
        *(uint2*)(hi + 4 * i) = make_uint2(h0, h1);
        *(uint2*)(lo + 4 * i) = make_uint2(l0, l1);
    }
}

// ---------------- s1/s2 from split h ----------------
__global__ __launch_bounds__(256)
void s12_kernel(const bf16* __restrict__ hhi, const bf16* __restrict__ hlo,
                const float* __restrict__ a1, const float* __restrict__ a2,
                float* __restrict__ s1, float* __restrict__ s2)
{
    int row = blockIdx.x;
    int t = threadIdx.x;
    size_t idx = (size_t)row * HH + t;
    float v = __bfloat162float(hhi[idx]) + __bfloat162float(hlo[idx]);
    float p1 = v * a1[t];
    float p2 = v * a2[t];
    p1 = warpSum(p1);
    p2 = warpSum(p2);
    __shared__ float r1[8], r2[8];
    if ((t & 31) == 0) { r1[t >> 5] = p1; r2[t >> 5] = p2; }
    __syncthreads();
    if (t == 0) {
        float t1 = 0.f, t2 = 0.f;
        #pragma unroll
        for (int w = 0; w < 8; w++) { t1 += r1[w]; t2 += r2[w]; }
        s1[row] = t1;
        s2[row] = t2;
    }
}

// ---------------- softmax row -> split bf16 attention ----------------
__global__ __launch_bounds__(256)
void stats_att_kernel(const float* __restrict__ adj, const float* __restrict__ s1,
                      const float* __restrict__ s2,
                      bf16* __restrict__ atthi, bf16* __restrict__ attlo)
{
    int bi = blockIdx.x;            // b*NN + i
    int b  = bi >> 10;
    const float* arow = adj + (size_t)bi * NN;
    const float* s2b  = s2 + b * NN;
    float s1i = s1[bi];
    int t = threadIdx.x;

    float e[4];
    float mx = -3.4e38f;
    #pragma unroll
    for (int k = 0; k < 4; k++) {
        int j = k * 256 + t;
        float sv = s1i + s2b[j];
        sv = sv >= 0.f ? sv : ALPHA * sv;
        float ev = (arow[j] > 0.f) ? sv : NEGV;
        e[k] = ev;
        mx = fmaxf(mx, ev);
    }
    __shared__ float redm[8], redz[8];
    float wm = warpMax(mx);
    if ((t & 31) == 0) redm[t >> 5] = wm;
    __syncthreads();
    float m = fmaxf(fmaxf(fmaxf(redm[0], redm[1]), fmaxf(redm[2], redm[3])),
                    fmaxf(fmaxf(redm[4], redm[5]), fmaxf(redm[6], redm[7])));

    float p[4];
    float zs = 0.f;
    #pragma unroll
    for (int k = 0; k < 4; k++) { p[k] = __expf(e[k] - m); zs += p[k]; }
    float ws = warpSum(zs);
    if ((t & 31) == 0) redz[t >> 5] = ws;
    __syncthreads();
    float z = redz[0] + redz[1] + redz[2] + redz[3] +
              redz[4] + redz[5] + redz[6] + redz[7];
    float rz = 1.f / z;

    size_t obase = (size_t)bi * NN;
    #pragma unroll
    for (int k = 0; k < 4; k++) {
        size_t idx = obase + k * 256 + t;
        float v = p[k] * rz;
        bf16 hb = __float2bfloat16(v);
        atthi[idx] = hb;
        attlo[idx] = __float2bfloat16(v - __bfloat162float(hb));
    }
}

// ---------------- pooling partials: sum & max over 128-row chunks ----------------
__global__ __launch_bounds__(256)
void pool_partial_kernel(const float* __restrict__ x, float* __restrict__ psum,
                         float* __restrict__ pmax)
{
    int b = blockIdx.y, c = blockIdx.x, hh = threadIdx.x;
    const float* xb = x + ((size_t)b * NN + c * 128) * HH + hh;
    float s = 0.f, mx = -3.4e38f;
    #pragma unroll 4
    for (int n = 0; n < 128; n++) {
        float v = xb[(size_t)n * HH];
        s += v;
        mx = fmaxf(mx, v);
    }
    psum[(b * 8 + c) * HH + hh] = s;
    pmax[(b * 8 + c) * HH + hh] = mx;
}

// ---------------- combine pooling + 2-layer MLP head ----------------
__global__ __launch_bounds__(256)
void pool_mlp_kernel(const float* __restrict__ psum, const float* __restrict__ pmax,
                     const float* __restrict__ W1, const float* __restrict__ b1,
                     const float* __restrict__ W2, const float* __restrict__ b2,
                     float* __restrict__ gout)
{
    int b = blockIdx.x, hh = threadIdx.x;
    __shared__ float g[HH], g1[HH];
    float s = 0.f, mx = -3.4e38f;
    #pragma unroll
    for (int c = 0; c < 8; c++) {
        s += psum[(b * 8 + c) * HH + hh];
        mx = fmaxf(mx, pmax[(b * 8 + c) * HH + hh]);
    }
    g[hh] = s * (1.f / (float)NN) + mx;
    __syncthreads();
    float acc = b1[hh];
    #pragma unroll 8
    for (int k = 0; k < HH; k++) acc = fmaf(g[k], W1[k * HH + hh], acc);
    g1[hh] = fmaxf(acc, 0.f);
    __syncthreads();
    float acc2 = b2[hh];
    #pragma unroll 8
    for (int k = 0; k < HH; k++) acc2 = fmaf(g1[k], W2[k * HH + hh], acc2);
    gout[b * HH + hh] = acc2;
}

// ---------------- host orchestration ----------------
extern "C" void kernel_launch(void* const* d_in, const int* in_sizes, int n_in,
                              void* d_out, int out_size)
{
    const float* nf   = (const float*)d_in[0];
    const float* adj  = (const float*)d_in[1];
    const float* embW = (const float*)d_in[2];
    const float* embb = (const float*)d_in[3];
    const float* W0   = (const float*)d_in[4];
    const float* a10  = (const float*)d_in[5];
    const float* a20  = (const float*)d_in[6];
    const float* W1   = (const float*)d_in[7];
    const float* a11  = (const float*)d_in[8];
    const float* a21  = (const float*)d_in[9];
    const float* gW1  = (const float*)d_in[10];
    const float* gb1  = (const float*)d_in[11];
    const float* gW2  = (const float*)d_in[12];
    const float* gb2  = (const float*)d_in[13];
    float* out = (float*)d_out;

    bf16 *nfh, *nfl, *eWh, *eWl, *W0h, *W0l, *W1h, *W1l;
    bf16 *xh, *xl, *hh, *hl, *yh, *yl, *ath, *atl;
    float *s1b, *s2b, *psb, *pmb;
    cudaGetSymbolAddress((void**)&nfh, g_nfhi); cudaGetSymbolAddress((void**)&nfl, g_nflo);
    cudaGetSymbolAddress((void**)&eWh, g_eWhi); cudaGetSymbolAddress((void**)&eWl, g_eWlo);
    cudaGetSymbolAddress((void**)&W0h, g_W0hi); cudaGetSymbolAddress((void**)&W0l, g_W0lo);
    cudaGetSymbolAddress((void**)&W1h, g_W1hi); cudaGetSymbolAddress((void**)&W1l, g_W1lo);
    cudaGetSymbolAddress((void**)&xh,  g_xhi);  cudaGetSymbolAddress((void**)&xl,  g_xlo);
    cudaGetSymbolAddress((void**)&hh,  g_hhi);  cudaGetSymbolAddress((void**)&hl,  g_hlo);
    cudaGetSymbolAddress((void**)&yh,  g_yhi);  cudaGetSymbolAddress((void**)&yl,  g_ylo);
    cudaGetSymbolAddress((void**)&ath, g_atthi);cudaGetSymbolAddress((void**)&atl, g_attlo);
    cudaGetSymbolAddress((void**)&s1b, g_s1);   cudaGetSymbolAddress((void**)&s2b, g_s2);
    cudaGetSymbolAddress((void**)&psb, g_ps);   cudaGetSymbolAddress((void**)&pmb, g_pm);

    cudaFuncSetAttribute(bgemm<true,  false, true >, cudaFuncAttributeMaxDynamicSharedMemorySize, GSMEM);
    cudaFuncSetAttribute(bgemm<false, false, true >, cudaFuncAttributeMaxDynamicSharedMemorySize, GSMEM);
    cudaFuncSetAttribute(bgemm<false, true,  true >, cudaFuncAttributeMaxDynamicSharedMemorySize, GSMEM);
    cudaFuncSetAttribute(bgemm<false, true,  false>, cudaFuncAttributeMaxDynamicSharedMemorySize, GSMEM);

    const int M = NB * NN;               // 16384
    float* xout = out;                           // [B,N,H] part of output
    float* gout = out + (out_size - NB * HH);    // [B,H]  part of output

    // ---- prep: split fp32 operands into bf16 hi/lo ----
    split_prep<<<(NB * NN * FIN / 4 + 255) / 256, 256>>>(nf,   nfh, nfl, NB * NN * FIN / 4);
    split_prep<<<(FIN * HH / 4 + 255) / 256, 256>>>(embW, eWh, eWl, FIN * HH / 4);
    split_prep<<<(HH * HH / 4 + 255) / 256, 256>>>(W0,   W0h, W0l, HH * HH / 4);
    split_prep<<<(HH * HH / 4 + 255) / 256, 256>>>(W1,   W1h, W1l, HH * HH / 4);

    // 1) emb: x = nf @ emb_W + emb_b  -> split bf16
    bgemm<true, false, true><<<dim3(HH / 128, M / 128, 1), 256, GSMEM>>>(
        nfh, nfl, eWh, eWl, embb, nullptr, xh, xl, M, FIN, HH, 0, 0, 0);

    // ---- GAT layer 0 ----
    bgemm<false, false, true><<<dim3(HH / 128, M / 128, 1), 256, GSMEM>>>(
        xh, xl, W0h, W0l, nullptr, nullptr, hh, hl, M, HH, HH, 0, 0, 0);
    s12_kernel<<<M, 256>>>(hh, hl, a10, a20, s1b, s2b);
    stats_att_kernel<<<M, 256>>>(adj, s1b, s2b, ath, atl);
    bgemm<false, true, true><<<dim3(HH / 128, NN / 128, NB), 256, GSMEM>>>(
        ath, atl, hh, hl, nullptr, nullptr, yh, yl, NN, NN, HH,
        (long long)NN * NN, (long long)NN * HH, (long long)NN * HH);

    // ---- GAT layer 1 ----
    bgemm<false, false, true><<<dim3(HH / 128, M / 128, 1), 256, GSMEM>>>(
        yh, yl, W1h, W1l, nullptr, nullptr, hh, hl, M, HH, HH, 0, 0, 0);
    s12_kernel<<<M, 256>>>(hh, hl, a11, a21, s1b, s2b);
    stats_att_kernel<<<M, 256>>>(adj, s1b, s2b, ath, atl);
    bgemm<false, true, false><<<dim3(HH / 128, NN / 128, NB), 256, GSMEM>>>(
        ath, atl, hh, hl, nullptr, xout, nullptr, nullptr, NN, NN, HH,
        (long long)NN * NN, (long long)NN * HH, (long long)NN * HH);

    // ---- pooling + MLP head ----
    pool_partial_kernel<<<dim3(8, NB), 256>>>(xout, psb, pmb);
    pool_mlp_kernel<<<NB, 256>>>(psb, pmb, gW1, gb1, gW2, gb2, gout);
}

// round 12
// speedup vs baseline: 1.1191x; 1.1191x over previous
#include <cuda_runtime.h>
#include <cuda_bf16.h>
#include <cuda_fp16.h>
#include <cstdint>

// Problem constants
#define NB  16
#define NN  1024
#define FIN 64
#define HH  256
#define NEGV  (-9e15f)
#define ALPHA 0.2f

typedef __nv_bfloat16 bf16;

// ---------------- scratch (device globals; no allocation allowed) ----------------
__device__ bf16 g_nfhi[NB * NN * FIN], g_nflo[NB * NN * FIN];
__device__ bf16 g_eWhi[FIN * HH],      g_eWlo[FIN * HH];
__device__ bf16 g_W0hi[HH * HH],       g_W0lo[HH * HH];
__device__ bf16 g_W1hi[HH * HH],       g_W1lo[HH * HH];
__device__ bf16 g_xhi [NB * NN * HH],  g_xlo [NB * NN * HH];
__device__ bf16 g_yhi [NB * NN * HH],  g_ylo [NB * NN * HH];
__device__ __half g_hhi[NB * NN * HH], g_hlo[NB * NN * HH];
__device__ __half g_att[(size_t)NB * NN * NN];             // fp16 single plane (33.5MB)
__device__ uint32_t g_mask[NB * NN * (NN / 32)];           // adjacency bitmask (2MB)
__device__ float g_s1 [NB * NN];
__device__ float g_s2 [NB * NN];
__device__ float g_ps [NB * 8 * HH];
__device__ float g_pm [NB * 8 * HH];

// ---------------- helpers ----------------
__device__ __forceinline__ uint32_t smem_u32(const void* p) {
    uint32_t a;
    asm("{ .reg .u64 t; cvta.to.shared.u64 t, %1; cvt.u32.u64 %0, t; }" : "=r"(a) : "l"(p));
    return a;
}
__device__ __forceinline__ void split_pair(float x, float y, uint32_t& hi, uint32_t& lo) {
    __nv_bfloat162 h = __floats2bfloat162_rn(x, y);
    float rx = x - __bfloat162float(__low2bfloat16(h));
    float ry = y - __bfloat162float(__high2bfloat16(h));
    __nv_bfloat162 l = __floats2bfloat162_rn(rx, ry);
    hi = *(uint32_t*)&h;
    lo = *(uint32_t*)&l;
}
__device__ __forceinline__ void split_pair_h(float x, float y, uint32_t& hi, uint32_t& lo) {
    __half2 h = __floats2half2_rn(x, y);
    float rx = x - __half2float(__low2half(h));
    float ry = y - __half2float(__high2half(h));
    __half2 l = __floats2half2_rn(rx, ry);
    hi = *(uint32_t*)&h;
    lo = *(uint32_t*)&l;
}

#define CP16(dst, src) \
    asm volatile("cp.async.cg.shared.global [%0], [%1], 16;" :: "r"(dst), "l"(src))
#define CP_COMMIT() asm volatile("cp.async.commit_group;")
#define CP_WAIT(n)  asm volatile("cp.async.wait_group %0;" :: "n"(n))

#define LDSM_X4(r0, r1, r2, r3, addr) \
    asm volatile("ldmatrix.sync.aligned.m8n8.x4.shared.b16 {%0,%1,%2,%3}, [%4];" \
                 : "=r"(r0), "=r"(r1), "=r"(r2), "=r"(r3) : "r"(addr))
#define LDSM_X4T(r0, r1, r2, r3, addr) \
    asm volatile("ldmatrix.sync.aligned.m8n8.x4.trans.shared.b16 {%0,%1,%2,%3}, [%4];" \
                 : "=r"(r0), "=r"(r1), "=r"(r2), "=r"(r3) : "r"(addr))
#define MMA_BF(d, a, b) \
    asm volatile("mma.sync.aligned.m16n8k16.row.col.f32.bf16.bf16.f32 " \
                 "{%0,%1,%2,%3}, {%4,%5,%6,%7}, {%8,%9}, {%0,%1,%2,%3};" \
                 : "+f"(d[0]), "+f"(d[1]), "+f"(d[2]), "+f"(d[3]) \
                 : "r"(a[0]), "r"(a[1]), "r"(a[2]), "r"(a[3]), "r"(b[0]), "r"(b[1]))
#define MMA_FP(d, a, b) \
    asm volatile("mma.sync.aligned.m16n8k16.row.col.f32.f16.f16.f32 " \
                 "{%0,%1,%2,%3}, {%4,%5,%6,%7}, {%8,%9}, {%0,%1,%2,%3};" \
                 : "+f"(d[0]), "+f"(d[1]), "+f"(d[2]), "+f"(d[3]) \
                 : "r"(a[0]), "r"(a[1]), "r"(a[2]), "r"(a[3]), "r"(b[0]), "r"(b[1]))

// ---------------- warp reductions ----------------
__device__ __forceinline__ float warpMax(float v) {
    #pragma unroll
    for (int o = 16; o > 0; o >>= 1) v = fmaxf(v, __shfl_xor_sync(0xFFFFFFFFu, v, o));
    return v;
}
__device__ __forceinline__ float warpSum(float v) {
    #pragma unroll
    for (int o = 16; o > 0; o >>= 1) v += __shfl_xor_sync(0xFFFFFFFFu, v, o);
    return v;
}

// ============================================================================
// bgemm: split-bf16 3-MMA GEMM (for emb and x@W). OUT: 0=fp32, 1=bf16 pair,
// 2=fp16 pair. Block 128x128, BK=32, 256 thr, warp tile 64x32, cp.async 2-stage.
// ============================================================================
#define APAD 40
#define BPAD 136
#define AL_OFF 10240
#define BH_OFF 20480
#define BL_OFF 29184
#define STAGE  37888
static constexpr int GSMEM = 2 * STAGE;

template<bool BIAS, bool RELU, int OUT>
__global__ __launch_bounds__(256)
void bgemm(const bf16* __restrict__ Ahi, const bf16* __restrict__ Alo,
           const bf16* __restrict__ Bhi, const bf16* __restrict__ Blo,
           const float* __restrict__ bias,
           void* __restrict__ Co1, void* __restrict__ Co2,
           int M, int K, int Nn)
{
    constexpr int BK = 32;
    extern __shared__ char dsm[];
    const uint32_t sb = smem_u32(dsm);

    const int bm = blockIdx.y * 128;
    const int bn = blockIdx.x * 128;
    const int tid  = threadIdx.x;
    const int lane = tid & 31;
    const int wid  = tid >> 5;
    const int m0 = (wid & 1) * 64, n0 = (wid >> 1) * 32;

    const uint32_t aoff = (uint32_t)(((m0 + (lane & 7) + ((lane >> 3) & 1) * 8) * APAD
                                     + (lane >> 4) * 8) * 2);
    const uint32_t boff = (uint32_t)((((lane & 7) + ((lane >> 3) & 1) * 8) * BPAD
                                     + n0 + (lane >> 4) * 8) * 2);

    float acc[4][4][4];
    #pragma unroll
    for (int mi = 0; mi < 4; mi++)
        #pragma unroll
        for (int ni = 0; ni < 4; ni++)
            #pragma unroll
            for (int r = 0; r < 4; r++) acc[mi][ni][r] = 0.f;

    const int nIter = K / BK;

    auto fill = [&](int stage, int k0) {
        uint32_t base = sb + stage * STAGE;
        #pragma unroll
        for (int l = 0; l < 2; l++) {
            int t = tid + (l << 8);
            int row = t >> 2, seg = t & 3;
            long long gsrc = (long long)(bm + row) * K + k0 + seg * 8;
            uint32_t d = base + row * 80 + seg * 16;
            CP16(d,          Ahi + gsrc);
            CP16(d + AL_OFF, Alo + gsrc);
        }
        #pragma unroll
        for (int l = 0; l < 2; l++) {
            int t = tid + (l << 8);
            int row = t >> 4, seg = t & 15;
            long long gsrc = (long long)(k0 + row) * Nn + bn + seg * 8;
            uint32_t d = base + BH_OFF + row * 272 + seg * 16;
            CP16(d,                     Bhi + gsrc);
            CP16(d + (BL_OFF - BH_OFF), Blo + gsrc);
        }
        CP_COMMIT();
    };

    fill(0, 0);

    for (int c = 0; c < nIter; ++c) {
        if (c + 1 < nIter) { fill((c + 1) & 1, (c + 1) * BK); CP_WAIT(1); }
        else               { CP_WAIT(0); }
        __syncthreads();

        const uint32_t base = sb + (c & 1) * STAGE;
        const uint32_t aHi = base,          aLo = base + AL_OFF;
        const uint32_t bHi = base + BH_OFF, bLo = base + BL_OFF;

        #pragma unroll
        for (int kk = 0; kk < BK; kk += 16) {
            uint32_t ah[4][4], al[4][4], bh[4][2], bl[4][2];
            #pragma unroll
            for (int mi = 0; mi < 4; mi++) {
                uint32_t d = (uint32_t)((mi * 16 * APAD + kk) * 2);
                LDSM_X4(ah[mi][0], ah[mi][1], ah[mi][2], ah[mi][3], aHi + aoff + d);
                LDSM_X4(al[mi][0], al[mi][1], al[mi][2], al[mi][3], aLo + aoff + d);
            }
            #pragma unroll
            for (int p = 0; p < 2; p++) {
                uint32_t d = (uint32_t)((kk * BPAD + p * 16) * 2);
                LDSM_X4T(bh[2 * p][0], bh[2 * p][1], bh[2 * p + 1][0], bh[2 * p + 1][1],
                         bHi + boff + d);
                LDSM_X4T(bl[2 * p][0], bl[2 * p][1], bl[2 * p + 1][0], bl[2 * p + 1][1],
                         bLo + boff + d);
            }
            #pragma unroll
            for (int mi = 0; mi < 4; mi++)
                #pragma unroll
                for (int ni = 0; ni < 4; ni++) {
                    MMA_BF(acc[mi][ni], ah[mi], bh[ni]);
                    MMA_BF(acc[mi][ni], ah[mi], bl[ni]);
                    MMA_BF(acc[mi][ni], al[mi], bh[ni]);
                }
        }
        __syncthreads();
    }

    const int rbase = bm + m0 + (lane >> 2);
    const int cbase = bn + n0 + 2 * (lane & 3);
    #pragma unroll
    for (int ni = 0; ni < 4; ni++) {
        int col = cbase + ni * 8;
        float2 bb = make_float2(0.f, 0.f);
        if (BIAS) bb = *(const float2*)(bias + col);
        #pragma unroll
        for (int mi = 0; mi < 4; mi++) {
            int r0 = rbase + mi * 16;
            float2 v0 = make_float2(acc[mi][ni][0] + bb.x, acc[mi][ni][1] + bb.y);
            float2 v1 = make_float2(acc[mi][ni][2] + bb.x, acc[mi][ni][3] + bb.y);
            if (RELU) {
                v0.x = fmaxf(v0.x, 0.f); v0.y = fmaxf(v0.y, 0.f);
                v1.x = fmaxf(v1.x, 0.f); v1.y = fmaxf(v1.y, 0.f);
            }
            long long o0 = (long long)r0 * Nn + col;
            long long o1 = (long long)(r0 + 8) * Nn + col;
            if (OUT == 0) {
                *(float2*)((float*)Co1 + o0) = v0;
                *(float2*)((float*)Co1 + o1) = v1;
            } else if (OUT == 1) {
                uint32_t h0, l0, h1, l1;
                split_pair(v0.x, v0.y, h0, l0);
                split_pair(v1.x, v1.y, h1, l1);
                *(uint32_t*)((bf16*)Co1 + o0) = h0;
                *(uint32_t*)((bf16*)Co2 + o0) = l0;
                *(uint32_t*)((bf16*)Co1 + o1) = h1;
                *(uint32_t*)((bf16*)Co2 + o1) = l1;
            } else {
                uint32_t h0, l0, h1, l1;
                split_pair_h(v0.x, v0.y, h0, l0);
                split_pair_h(v1.x, v1.y, h1, l1);
                *(uint32_t*)((__half*)Co1 + o0) = h0;
                *(uint32_t*)((__half*)Co2 + o0) = l0;
                *(uint32_t*)((__half*)Co1 + o1) = h1;
                *(uint32_t*)((__half*)Co2 + o1) = l1;
            }
        }
    }
}

// ============================================================================
// agemm: attention GEMM, A = att fp16 single, B = h fp16 hi/lo -> 2 MMAs/k16.
// C = att[NN,NN] @ h[NN,HH], relu. OUT: 0=fp32, 1=bf16 pair. Batched (z).
// ============================================================================
#define A_BH_OFF 10240
#define A_BL_OFF 18944
#define A_STAGE  27648
static constexpr int ASMEM = 2 * A_STAGE;

template<int OUT>
__global__ __launch_bounds__(256)
void agemm(const __half* __restrict__ Ag, const __half* __restrict__ Bhig,
           const __half* __restrict__ Blog,
           void* __restrict__ Co1, void* __restrict__ Co2)
{
    constexpr int BK = 32, K = NN, Nn = HH;
    extern __shared__ char dsm[];
    const uint32_t sb = smem_u32(dsm);

    const long long zA = (long long)blockIdx.z * NN * NN;
    const long long zB = (long long)blockIdx.z * NN * HH;
    const long long zC = (long long)blockIdx.z * NN * HH;
    const __half* A  = Ag + zA;
    const __half* Bh = Bhig + zB;
    const __half* Bl = Blog + zB;

    const int bm = blockIdx.y * 128;
    const int bn = blockIdx.x * 128;
    const int tid  = threadIdx.x;
    const int lane = tid & 31;
    const int wid  = tid >> 5;
    const int m0 = (wid & 1) * 64, n0 = (wid >> 1) * 32;

    const uint32_t aoff = (uint32_t)(((m0 + (lane & 7) + ((lane >> 3) & 1) * 8) * APAD
                                     + (lane >> 4) * 8) * 2);
    const uint32_t boff = (uint32_t)((((lane & 7) + ((lane >> 3) & 1) * 8) * BPAD
                                     + n0 + (lane >> 4) * 8) * 2);

    float acc[4][4][4];
    #pragma unroll
    for (int mi = 0; mi < 4; mi++)
        #pragma unroll
        for (int ni = 0; ni < 4; ni++)
            #pragma unroll
            for (int r = 0; r < 4; r++) acc[mi][ni][r] = 0.f;

    const int nIter = K / BK;

    auto fill = [&](int stage, int k0) {
        uint32_t base = sb + stage * A_STAGE;
        #pragma unroll
        for (int l = 0; l < 2; l++) {
            int t = tid + (l << 8);
            int row = t >> 2, seg = t & 3;
            long long gsrc = (long long)(bm + row) * K + k0 + seg * 8;
            CP16(base + row * 80 + seg * 16, A + gsrc);
        }
        #pragma unroll
        for (int l = 0; l < 2; l++) {
            int t = tid + (l << 8);
            int row = t >> 4, seg = t & 15;
            long long gsrc = (long long)(k0 + row) * Nn + bn + seg * 8;
            uint32_t d = base + A_BH_OFF + row * 272 + seg * 16;
            CP16(d, Bh + gsrc);
            CP16(d + (A_BL_OFF - A_BH_OFF), Bl + gsrc);
        }
        CP_COMMIT();
    };

    fill(0, 0);

    for (int c = 0; c < nIter; ++c) {
        if (c + 1 < nIter) { fill((c + 1) & 1, (c + 1) * BK); CP_WAIT(1); }
        else               { CP_WAIT(0); }
        __syncthreads();

        const uint32_t base = sb + (c & 1) * A_STAGE;
        const uint32_t aB = base;
        const uint32_t bHi = base + A_BH_OFF, bLo = base + A_BL_OFF;

        #pragma unroll
        for (int kk = 0; kk < BK; kk += 16) {
            uint32_t ah[4][4], bh[4][2], bl[4][2];
            #pragma unroll
            for (int mi = 0; mi < 4; mi++) {
                uint32_t d = (uint32_t)((mi * 16 * APAD + kk) * 2);
                LDSM_X4(ah[mi][0], ah[mi][1], ah[mi][2], ah[mi][3], aB + aoff + d);
            }
            #pragma unroll
            for (int p = 0; p < 2; p++) {
                uint32_t d = (uint32_t)((kk * BPAD + p * 16) * 2);
                LDSM_X4T(bh[2 * p][0], bh[2 * p][1], bh[2 * p + 1][0], bh[2 * p + 1][1],
                         bHi + boff + d);
                LDSM_X4T(bl[2 * p][0], bl[2 * p][1], bl[2 * p + 1][0], bl[2 * p + 1][1],
                         bLo + boff + d);
            }
            #pragma unroll
            for (int mi = 0; mi < 4; mi++)
                #pragma unroll
                for (int ni = 0; ni < 4; ni++) {
                    MMA_FP(acc[mi][ni], ah[mi], bh[ni]);
                    MMA_FP(acc[mi][ni], ah[mi], bl[ni]);
                }
        }
        __syncthreads();
    }

    const int rbase = bm + m0 + (lane >> 2);
    const int cbase = bn + n0 + 2 * (lane & 3);
    #pragma unroll
    for (int ni = 0; ni < 4; ni++) {
        int col = cbase + ni * 8;
        #pragma unroll
        for (int mi = 0; mi < 4; mi++) {
            int r0 = rbase + mi * 16;
            float2 v0 = make_float2(fmaxf(acc[mi][ni][0], 0.f), fmaxf(acc[mi][ni][1], 0.f));
            float2 v1 = make_float2(fmaxf(acc[mi][ni][2], 0.f), fmaxf(acc[mi][ni][3], 0.f));
            long long o0 = zC + (long long)r0 * Nn + col;
            long long o1 = zC + (long long)(r0 + 8) * Nn + col;
            if (OUT == 0) {
                *(float2*)((float*)Co1 + o0) = v0;
                *(float2*)((float*)Co1 + o1) = v1;
            } else {
                uint32_t h0, l0, h1, l1;
                split_pair(v0.x, v0.y, h0, l0);
                split_pair(v1.x, v1.y, h1, l1);
                *(uint32_t*)((bf16*)Co1 + o0) = h0;
                *(uint32_t*)((bf16*)Co2 + o0) = l0;
                *(uint32_t*)((bf16*)Co1 + o1) = h1;
                *(uint32_t*)((bf16*)Co2 + o1) = l1;
            }
        }
    }
}

// ---------------- fused split prep: nf, embW, W0, W1 in one launch ----------------
#define S0 (NB * NN * FIN / 4)
#define S1 (FIN * HH / 4)
#define S2 (HH * HH / 4)
__global__ __launch_bounds__(256)
void split_all(const float* __restrict__ nf, const float* __restrict__ eW,
               const float* __restrict__ W0, const float* __restrict__ W1,
               bf16* nfh, bf16* nfl, bf16* eWh, bf16* eWl,
               bf16* W0h, bf16* W0l, bf16* W1h, bf16* W1l)
{
    int i = blockIdx.x * 256 + threadIdx.x;
    const float* src; bf16 *ph, *pl; int off;
    if (i < S0)                { src = nf; ph = nfh; pl = nfl; off = i; }
    else if (i < S0 + S1)      { src = eW; ph = eWh; pl = eWl; off = i - S0; }
    else if (i < S0 + S1 + S2) { src = W0; ph = W0h; pl = W0l; off = i - S0 - S1; }
    else if (i < S0 + S1 + 2 * S2) { src = W1; ph = W1h; pl = W1l; off = i - S0 - S1 - S2; }
    else return;
    float4 v = ((const float4*)src)[off];
    uint32_t h0, l0, h1, l1;
    split_pair(v.x, v.y, h0, l0);
    split_pair(v.z, v.w, h1, l1);
    *(uint2*)(ph + 4 * off) = make_uint2(h0, h1);
    *(uint2*)(pl + 4 * off) = make_uint2(l0, l1);
}

// ---------------- adjacency -> bitmask (ballot) ----------------
__global__ __launch_bounds__(256)
void adj2mask(const float* __restrict__ adj, uint32_t* __restrict__ mask)
{
    int lane = threadIdx.x & 31;
    int gw = blockIdx.x * 8 + (threadIdx.x >> 5);   // global warp id
    #pragma unroll
    for (int i = 0; i < 8; i++) {
        size_t w = (size_t)gw * 8 + i;              // word index
        float v = adj[w * 32 + lane];
        uint32_t b = __ballot_sync(0xFFFFFFFFu, v > 0.f);
        if (lane == 0) mask[w] = b;
    }
}

// ---------------- s1/s2 from fp16 split h ----------------
__global__ __launch_bounds__(256)
void s12_kernel(const __half* __restrict__ hhi, const __half* __restrict__ hlo,
                const float* __restrict__ a1, const float* __restrict__ a2,
                float* __restrict__ s1, float* __restrict__ s2)
{
    int row = blockIdx.x;
    int t = threadIdx.x;
    size_t idx = (size_t)row * HH + t;
    float v = __half2float(hhi[idx]) + __half2float(hlo[idx]);
    float p1 = v * a1[t];
    float p2 = v * a2[t];
    p1 = warpSum(p1);
    p2 = warpSum(p2);
    __shared__ float r1[8], r2[8];
    if ((t & 31) == 0) { r1[t >> 5] = p1; r2[t >> 5] = p2; }
    __syncthreads();
    if (t == 0) {
        float t1 = 0.f, t2 = 0.f;
        #pragma unroll
        for (int w = 0; w < 8; w++) { t1 += r1[w]; t2 += r2[w]; }
        s1[row] = t1;
        s2[row] = t2;
    }
}

// ---------------- softmax row from bitmask -> fp16 attention ----------------
__global__ __launch_bounds__(256)
void stats_att_kernel(const uint32_t* __restrict__ mask, const float* __restrict__ s1,
                      const float* __restrict__ s2, __half* __restrict__ att)
{
    int bi = blockIdx.x;            // b*NN + i
    int b  = bi >> 10;
    const uint32_t* mrow = mask + (size_t)bi * (NN / 32);
    const float* s2b = s2 + b * NN;
    float s1i = s1[bi];
    int t = threadIdx.x;

    float e[4];
    float mx = -3.4e38f;
    #pragma unroll
    for (int k = 0; k < 4; k++) {
        int j = k * 256 + t;
        float sv = s1i + s2b[j];
        sv = sv >= 0.f ? sv : ALPHA * sv;
        bool on = (mrow[j >> 5] >> (j & 31)) & 1u;
        float ev = on ? sv : NEGV;
        e[k] = ev;
        mx = fmaxf(mx, ev);
    }
    __shared__ float redm[8], redz[8];
    float wm = warpMax(mx);
    if ((t & 31) == 0) redm[t >> 5] = wm;
    __syncthreads();
    float m = fmaxf(fmaxf(fmaxf(redm[0], redm[1]), fmaxf(redm[2], redm[3])),
                    fmaxf(fmaxf(redm[4], redm[5]), fmaxf(redm[6], redm[7])));

    float p[4];
    float zs = 0.f;
    #pragma unroll
    for (int k = 0; k < 4; k++) { p[k] = __expf(e[k] - m); zs += p[k]; }
    float ws = warpSum(zs);
    if ((t & 31) == 0) redz[t >> 5] = ws;
    __syncthreads();
    float z = redz[0] + redz[1] + redz[2] + redz[3] +
              redz[4] + redz[5] + redz[6] + redz[7];
    float rz = 1.f / z;

    size_t obase = (size_t)bi * NN;
    #pragma unroll
    for (int k = 0; k < 4; k++)
        att[obase + k * 256 + t] = __float2half_rn(p[k] * rz);
}

// ---------------- pooling partials ----------------
__global__ __launch_bounds__(256)
void pool_partial_kernel(const float* __restrict__ x, float* __restrict__ psum,
                         float* __restrict__ pmax)
{
    int b = blockIdx.y, c = blockIdx.x, hh = threadIdx.x;
    const float* xb = x + ((size_t)b * NN + c * 128) * HH + hh;
    float s = 0.f, mx = -3.4e38f;
    #pragma unroll 4
    for (int n = 0; n < 128; n++) {
        float v = xb[(size_t)n * HH];
        s += v;
        mx = fmaxf(mx, v);
    }
    psum[(b * 8 + c) * HH + hh] = s;
    pmax[(b * 8 + c) * HH + hh] = mx;
}

// ---------------- combine pooling + 2-layer MLP head ----------------
__global__ __launch_bounds__(256)
void pool_mlp_kernel(const float* __restrict__ psum, const float* __restrict__ pmax,
                     const float* __restrict__ W1, const float* __restrict__ b1,
                     const float* __restrict__ W2, const float* __restrict__ b2,
                     float* __restrict__ gout)
{
    int b = blockIdx.x, hh = threadIdx.x;
    __shared__ float g[HH], g1[HH];
    float s = 0.f, mx = -3.4e38f;
    #pragma unroll
    for (int c = 0; c < 8; c++) {
        s += psum[(b * 8 + c) * HH + hh];
        mx = fmaxf(mx, pmax[(b * 8 + c) * HH + hh]);
    }
    g[hh] = s * (1.f / (float)NN) + mx;
    __syncthreads();
    float acc = b1[hh];
    #pragma unroll 8
    for (int k = 0; k < HH; k++) acc = fmaf(g[k], W1[k * HH + hh], acc);
    g1[hh] = fmaxf(acc, 0.f);
    __syncthreads();
    float acc2 = b2[hh];
    #pragma unroll 8
    for (int k = 0; k < HH; k++) acc2 = fmaf(g1[k], W2[k * HH + hh], acc2);
    gout[b * HH + hh] = acc2;
}

// ---------------- host orchestration ----------------
extern "C" void kernel_launch(void* const* d_in, const int* in_sizes, int n_in,
                              void* d_out, int out_size)
{
    const float* nf   = (const float*)d_in[0];
    const float* adj  = (const float*)d_in[1];
    const float* embW = (const float*)d_in[2];
    const float* embb = (const float*)d_in[3];
    const float* W0   = (const float*)d_in[4];
    const float* a10  = (const float*)d_in[5];
    const float* a20  = (const float*)d_in[6];
    const float* W1   = (const float*)d_in[7];
    const float* a11  = (const float*)d_in[8];
    const float* a21  = (const float*)d_in[9];
    const float* gW1  = (const float*)d_in[10];
    const float* gb1  = (const float*)d_in[11];
    const float* gW2  = (const float*)d_in[12];
    const float* gb2  = (const float*)d_in[13];
    float* out = (float*)d_out;

    bf16 *nfh, *nfl, *eWh, *eWl, *W0h, *W0l, *W1h, *W1l, *xh, *xl, *yh, *yl;
    __half *hh, *hl, *attp;
    uint32_t* maskp;
    float *s1b, *s2b, *psb, *pmb;
    cudaGetSymbolAddress((void**)&nfh, g_nfhi); cudaGetSymbolAddress((void**)&nfl, g_nflo);
    cudaGetSymbolAddress((void**)&eWh, g_eWhi); cudaGetSymbolAddress((void**)&eWl, g_eWlo);
    cudaGetSymbolAddress((void**)&W0h, g_W0hi); cudaGetSymbolAddress((void**)&W0l, g_W0lo);
    cudaGetSymbolAddress((void**)&W1h, g_W1hi); cudaGetSymbolAddress((void**)&W1l, g_W1lo);
    cudaGetSymbolAddress((void**)&xh,  g_xhi);  cudaGetSymbolAddress((void**)&xl,  g_xlo);
    cudaGetSymbolAddress((void**)&yh,  g_yhi);  cudaGetSymbolAddress((void**)&yl,  g_ylo);
    cudaGetSymbolAddress((void**)&hh,  g_hhi);  cudaGetSymbolAddress((void**)&hl,  g_hlo);
    cudaGetSymbolAddress((void**)&attp, g_att);
    cudaGetSymbolAddress((void**)&maskp, g_mask);
    cudaGetSymbolAddress((void**)&s1b, g_s1);   cudaGetSymbolAddress((void**)&s2b, g_s2);
    cudaGetSymbolAddress((void**)&psb, g_ps);   cudaGetSymbolAddress((void**)&pmb, g_pm);

    cudaFuncSetAttribute(bgemm<true,  false, 1>, cudaFuncAttributeMaxDynamicSharedMemorySize, GSMEM);
    cudaFuncSetAttribute(bgemm<false, false, 2>, cudaFuncAttributeMaxDynamicSharedMemorySize, GSMEM);
    cudaFuncSetAttribute(agemm<1>, cudaFuncAttributeMaxDynamicSharedMemorySize, ASMEM);
    cudaFuncSetAttribute(agemm<0>, cudaFuncAttributeMaxDynamicSharedMemorySize, ASMEM);

    const int M = NB * NN;               // 16384
    float* xout = out;                           // [B,N,H] part of output
    float* gout = out + (out_size - NB * HH);    // [B,H]  part of output

    // ---- prep ----
    split_all<<<(S0 + S1 + 2 * S2 + 255) / 256, 256>>>(
        nf, embW, W0, W1, nfh, nfl, eWh, eWl, W0h, W0l, W1h, W1l);
    adj2mask<<<NB * NN * (NN / 32) / 64, 256>>>(adj, maskp);

    // 1) emb: x = nf @ emb_W + emb_b  -> bf16 pair
    bgemm<true, false, 1><<<dim3(HH / 128, M / 128, 1), 256, GSMEM>>>(
        nfh, nfl, eWh, eWl, embb, xh, xl, M, FIN, HH);

    // ---- GAT layer 0 ----
    bgemm<false, false, 2><<<dim3(HH / 128, M / 128, 1), 256, GSMEM>>>(
        xh, xl, W0h, W0l, nullptr, hh, hl, M, HH, HH);
    s12_kernel<<<M, 256>>>(hh, hl, a10, a20, s1b, s2b);
    stats_att_kernel<<<M, 256>>>(maskp, s1b, s2b, attp);
    agemm<1><<<dim3(HH / 128, NN / 128, NB), 256, ASMEM>>>(attp, hh, hl, yh, yl);

    // ---- GAT layer 1 ----
    bgemm<false, false, 2><<<dim3(HH / 128, M / 128, 1), 256, GSMEM>>>(
        yh, yl, W1h, W1l, nullptr, hh, hl, M, HH, HH);
    s12_kernel<<<M, 256>>>(hh, hl, a11, a21, s1b, s2b);
    stats_att_kernel<<<M, 256>>>(maskp, s1b, s2b, attp);
    agemm<0><<<dim3(HH / 128, NN / 128, NB), 256, ASMEM>>>(attp, hh, hl, xout, nullptr);

    // ---- pooling + MLP head ----
    pool_partial_kernel<<<dim3(8, NB), 256>>>(xout, psb, pmb);
    pool_mlp_kernel<<<NB, 256>>>(psb, pmb, gW1, gb1, gW2, gb2, gout);
}

// round 13
// speedup vs baseline: 1.4544x; 1.2996x over previous
#include <cuda_runtime.h>
#include <cuda_bf16.h>
#include <cuda_fp16.h>
#include <cstdint>

// Problem constants
#define NB  16
#define NN  1024
#define FIN 64
#define HH  256
#define NEGV  (-9e15f)
#define ALPHA 0.2f

typedef __nv_bfloat16 bf16;

// ---------------- scratch (device globals; no allocation allowed) ----------------
__device__ bf16 g_nfhi[NB * NN * FIN], g_nflo[NB * NN * FIN];
__device__ bf16 g_eWhi[FIN * HH],      g_eWlo[FIN * HH];
__device__ __half g_W0f[HH * HH],      g_W1f[HH * HH];        // fp16 single weights
__device__ __half g_xhi[NB * NN * HH], g_xlo[NB * NN * HH];   // x fp16 pair
__device__ __half g_yhi[NB * NN * HH], g_ylo[NB * NN * HH];   // y fp16 pair
__device__ __half g_hh [NB * NN * HH];                        // h fp16 single
__device__ __half g_att[(size_t)NB * NN * NN];                // att fp16 single (33.5MB)
__device__ uint32_t g_mask[NB * NN * (NN / 32)];              // adjacency bitmask (2MB)
__device__ float g_s1 [NB * NN];
__device__ float g_s2 [NB * NN];
__device__ float g_ps [NB * 8 * HH];
__device__ float g_pm [NB * 8 * HH];

// ---------------- helpers ----------------
__device__ __forceinline__ uint32_t smem_u32(const void* p) {
    uint32_t a;
    asm("{ .reg .u64 t; cvta.to.shared.u64 t, %1; cvt.u32.u64 %0, t; }" : "=r"(a) : "l"(p));
    return a;
}
__device__ __forceinline__ void split_pair(float x, float y, uint32_t& hi, uint32_t& lo) {
    __nv_bfloat162 h = __floats2bfloat162_rn(x, y);
    float rx = x - __bfloat162float(__low2bfloat16(h));
    float ry = y - __bfloat162float(__high2bfloat16(h));
    __nv_bfloat162 l = __floats2bfloat162_rn(rx, ry);
    hi = *(uint32_t*)&h;
    lo = *(uint32_t*)&l;
}
__device__ __forceinline__ void split_pair_h(float x, float y, uint32_t& hi, uint32_t& lo) {
    __half2 h = __floats2half2_rn(x, y);
    float rx = x - __half2float(__low2half(h));
    float ry = y - __half2float(__high2half(h));
    __half2 l = __floats2half2_rn(rx, ry);
    hi = *(uint32_t*)&h;
    lo = *(uint32_t*)&l;
}

#define CP16(dst, src) \
    asm volatile("cp.async.cg.shared.global [%0], [%1], 16;" :: "r"(dst), "l"(src))
#define CP_COMMIT() asm volatile("cp.async.commit_group;")
#define CP_WAIT(n)  asm volatile("cp.async.wait_group %0;" :: "n"(n))

#define LDSM_X4(r0, r1, r2, r3, addr) \
    asm volatile("ldmatrix.sync.aligned.m8n8.x4.shared.b16 {%0,%1,%2,%3}, [%4];" \
                 : "=r"(r0), "=r"(r1), "=r"(r2), "=r"(r3) : "r"(addr))
#define LDSM_X4T(r0, r1, r2, r3, addr) \
    asm volatile("ldmatrix.sync.aligned.m8n8.x4.trans.shared.b16 {%0,%1,%2,%3}, [%4];" \
                 : "=r"(r0), "=r"(r1), "=r"(r2), "=r"(r3) : "r"(addr))
#define MMA_BF(d, a, b) \
    asm volatile("mma.sync.aligned.m16n8k16.row.col.f32.bf16.bf16.f32 " \
                 "{%0,%1,%2,%3}, {%4,%5,%6,%7}, {%8,%9}, {%0,%1,%2,%3};" \
                 : "+f"(d[0]), "+f"(d[1]), "+f"(d[2]), "+f"(d[3]) \
                 : "r"(a[0]), "r"(a[1]), "r"(a[2]), "r"(a[3]), "r"(b[0]), "r"(b[1]))
#define MMA_FP(d, a, b) \
    asm volatile("mma.sync.aligned.m16n8k16.row.col.f32.f16.f16.f32 " \
                 "{%0,%1,%2,%3}, {%4,%5,%6,%7}, {%8,%9}, {%0,%1,%2,%3};" \
                 : "+f"(d[0]), "+f"(d[1]), "+f"(d[2]), "+f"(d[3]) \
                 : "r"(a[0]), "r"(a[1]), "r"(a[2]), "r"(a[3]), "r"(b[0]), "r"(b[1]))

// ---------------- warp reductions ----------------
__device__ __forceinline__ float warpMax(float v) {
    #pragma unroll
    for (int o = 16; o > 0; o >>= 1) v = fmaxf(v, __shfl_xor_sync(0xFFFFFFFFu, v, o));
    return v;
}
__device__ __forceinline__ float warpSum(float v) {
    #pragma unroll
    for (int o = 16; o > 0; o >>= 1) v += __shfl_xor_sync(0xFFFFFFFFu, v, o);
    return v;
}

// Common geometry: block 128x128, BK=32, 256 thr, 8 warps (64x32 warp tiles)
#define APAD 40
#define BPAD 136

// ============================================================================
// bgemm: split-bf16 3-MMA GEMM (emb only). Out = fp16 pair + bias.
// ============================================================================
#define B_AL_OFF 10240
#define B_BH_OFF 20480
#define B_BL_OFF 29184
#define B_STAGE  37888
static constexpr int GSMEM = 2 * B_STAGE;

__global__ __launch_bounds__(256)
void bgemm(const bf16* __restrict__ Ahi, const bf16* __restrict__ Alo,
           const bf16* __restrict__ Bhi, const bf16* __restrict__ Blo,
           const float* __restrict__ bias,
           __half* __restrict__ Chi, __half* __restrict__ Clo,
           int M, int K, int Nn)
{
    constexpr int BK = 32;
    extern __shared__ char dsm[];
    const uint32_t sb = smem_u32(dsm);

    const int bm = blockIdx.y * 128;
    const int bn = blockIdx.x * 128;
    const int tid  = threadIdx.x;
    const int lane = tid & 31;
    const int wid  = tid >> 5;
    const int m0 = (wid & 1) * 64, n0 = (wid >> 1) * 32;

    const uint32_t aoff = (uint32_t)(((m0 + (lane & 7) + ((lane >> 3) & 1) * 8) * APAD
                                     + (lane >> 4) * 8) * 2);
    const uint32_t boff = (uint32_t)((((lane & 7) + ((lane >> 3) & 1) * 8) * BPAD
                                     + n0 + (lane >> 4) * 8) * 2);

    float acc[4][4][4];
    #pragma unroll
    for (int mi = 0; mi < 4; mi++)
        #pragma unroll
        for (int ni = 0; ni < 4; ni++)
            #pragma unroll
            for (int r = 0; r < 4; r++) acc[mi][ni][r] = 0.f;

    const int nIter = K / BK;

    auto fill = [&](int stage, int k0) {
        uint32_t base = sb + stage * B_STAGE;
        #pragma unroll
        for (int l = 0; l < 2; l++) {
            int t = tid + (l << 8);
            int row = t >> 2, seg = t & 3;
            long long gsrc = (long long)(bm + row) * K + k0 + seg * 8;
            uint32_t d = base + row * 80 + seg * 16;
            CP16(d,            Ahi + gsrc);
            CP16(d + B_AL_OFF, Alo + gsrc);
        }
        #pragma unroll
        for (int l = 0; l < 2; l++) {
            int t = tid + (l << 8);
            int row = t >> 4, seg = t & 15;
            long long gsrc = (long long)(k0 + row) * Nn + bn + seg * 8;
            uint32_t d = base + B_BH_OFF + row * 272 + seg * 16;
            CP16(d,                         Bhi + gsrc);
            CP16(d + (B_BL_OFF - B_BH_OFF), Blo + gsrc);
        }
        CP_COMMIT();
    };

    fill(0, 0);

    for (int c = 0; c < nIter; ++c) {
        if (c + 1 < nIter) { fill((c + 1) & 1, (c + 1) * BK); CP_WAIT(1); }
        else               { CP_WAIT(0); }
        __syncthreads();

        const uint32_t base = sb + (c & 1) * B_STAGE;
        const uint32_t aHi = base,            aLo = base + B_AL_OFF;
        const uint32_t bHi = base + B_BH_OFF, bLo = base + B_BL_OFF;

        #pragma unroll
        for (int kk = 0; kk < BK; kk += 16) {
            uint32_t ah[4][4], al[4][4], bh[4][2], bl[4][2];
            #pragma unroll
            for (int mi = 0; mi < 4; mi++) {
                uint32_t d = (uint32_t)((mi * 16 * APAD + kk) * 2);
                LDSM_X4(ah[mi][0], ah[mi][1], ah[mi][2], ah[mi][3], aHi + aoff + d);
                LDSM_X4(al[mi][0], al[mi][1], al[mi][2], al[mi][3], aLo + aoff + d);
            }
            #pragma unroll
            for (int p = 0; p < 2; p++) {
                uint32_t d = (uint32_t)((kk * BPAD + p * 16) * 2);
                LDSM_X4T(bh[2 * p][0], bh[2 * p][1], bh[2 * p + 1][0], bh[2 * p + 1][1],
                         bHi + boff + d);
                LDSM_X4T(bl[2 * p][0], bl[2 * p][1], bl[2 * p + 1][0], bl[2 * p + 1][1],
                         bLo + boff + d);
            }
            #pragma unroll
            for (int mi = 0; mi < 4; mi++)
                #pragma unroll
                for (int ni = 0; ni < 4; ni++) {
                    MMA_BF(acc[mi][ni], ah[mi], bh[ni]);
                    MMA_BF(acc[mi][ni], ah[mi], bl[ni]);
                    MMA_BF(acc[mi][ni], al[mi], bh[ni]);
                }
        }
        __syncthreads();
    }

    const int rbase = bm + m0 + (lane >> 2);
    const int cbase = bn + n0 + 2 * (lane & 3);
    #pragma unroll
    for (int ni = 0; ni < 4; ni++) {
        int col = cbase + ni * 8;
        float2 bb = *(const float2*)(bias + col);
        #pragma unroll
        for (int mi = 0; mi < 4; mi++) {
            int r0 = rbase + mi * 16;
            long long o0 = (long long)r0 * Nn + col;
            long long o1 = (long long)(r0 + 8) * Nn + col;
            uint32_t h0, l0, h1, l1;
            split_pair_h(acc[mi][ni][0] + bb.x, acc[mi][ni][1] + bb.y, h0, l0);
            split_pair_h(acc[mi][ni][2] + bb.x, acc[mi][ni][3] + bb.y, h1, l1);
            *(uint32_t*)(Chi + o0) = h0;
            *(uint32_t*)(Clo + o0) = l0;
            *(uint32_t*)(Chi + o1) = h1;
            *(uint32_t*)(Clo + o1) = l1;
        }
    }
}

// ============================================================================
// hgemm: x@W. A = fp16 pair, B = fp16 single -> 2 MMAs/k16. Out h fp16 single.
// ============================================================================
#define H_AL_OFF 10240
#define H_B_OFF  20480
#define H_STAGE  29184
static constexpr int HSMEM = 2 * H_STAGE;

__global__ __launch_bounds__(256)
void hgemm(const __half* __restrict__ Ahi, const __half* __restrict__ Alo,
           const __half* __restrict__ Bw, __half* __restrict__ Ch,
           int M, int K, int Nn)
{
    constexpr int BK = 32;
    extern __shared__ char dsm[];
    const uint32_t sb = smem_u32(dsm);

    const int bm = blockIdx.y * 128;
    const int bn = blockIdx.x * 128;
    const int tid  = threadIdx.x;
    const int lane = tid & 31;
    const int wid  = tid >> 5;
    const int m0 = (wid & 1) * 64, n0 = (wid >> 1) * 32;

    const uint32_t aoff = (uint32_t)(((m0 + (lane & 7) + ((lane >> 3) & 1) * 8) * APAD
                                     + (lane >> 4) * 8) * 2);
    const uint32_t boff = (uint32_t)((((lane & 7) + ((lane >> 3) & 1) * 8) * BPAD
                                     + n0 + (lane >> 4) * 8) * 2);

    float acc[4][4][4];
    #pragma unroll
    for (int mi = 0; mi < 4; mi++)
        #pragma unroll
        for (int ni = 0; ni < 4; ni++)
            #pragma unroll
            for (int r = 0; r < 4; r++) acc[mi][ni][r] = 0.f;

    const int nIter = K / BK;

    auto fill = [&](int stage, int k0) {
        uint32_t base = sb + stage * H_STAGE;
        #pragma unroll
        for (int l = 0; l < 2; l++) {
            int t = tid + (l << 8);
            int row = t >> 2, seg = t & 3;
            long long gsrc = (long long)(bm + row) * K + k0 + seg * 8;
            uint32_t d = base + row * 80 + seg * 16;
            CP16(d,            Ahi + gsrc);
            CP16(d + H_AL_OFF, Alo + gsrc);
        }
        #pragma unroll
        for (int l = 0; l < 2; l++) {
            int t = tid + (l << 8);
            int row = t >> 4, seg = t & 15;
            long long gsrc = (long long)(k0 + row) * Nn + bn + seg * 8;
            CP16(base + H_B_OFF + row * 272 + seg * 16, Bw + gsrc);
        }
        CP_COMMIT();
    };

    fill(0, 0);

    for (int c = 0; c < nIter; ++c) {
        if (c + 1 < nIter) { fill((c + 1) & 1, (c + 1) * BK); CP_WAIT(1); }
        else               { CP_WAIT(0); }
        __syncthreads();

        const uint32_t base = sb + (c & 1) * H_STAGE;
        const uint32_t aHi = base, aLo = base + H_AL_OFF, bB = base + H_B_OFF;

        #pragma unroll
        for (int kk = 0; kk < BK; kk += 16) {
            uint32_t ah[4][4], al[4][4], bh[4][2];
            #pragma unroll
            for (int mi = 0; mi < 4; mi++) {
                uint32_t d = (uint32_t)((mi * 16 * APAD + kk) * 2);
                LDSM_X4(ah[mi][0], ah[mi][1], ah[mi][2], ah[mi][3], aHi + aoff + d);
                LDSM_X4(al[mi][0], al[mi][1], al[mi][2], al[mi][3], aLo + aoff + d);
            }
            #pragma unroll
            for (int p = 0; p < 2; p++) {
                uint32_t d = (uint32_t)((kk * BPAD + p * 16) * 2);
                LDSM_X4T(bh[2 * p][0], bh[2 * p][1], bh[2 * p + 1][0], bh[2 * p + 1][1],
                         bB + boff + d);
            }
            #pragma unroll
            for (int mi = 0; mi < 4; mi++)
                #pragma unroll
                for (int ni = 0; ni < 4; ni++) {
                    MMA_FP(acc[mi][ni], ah[mi], bh[ni]);
                    MMA_FP(acc[mi][ni], al[mi], bh[ni]);
                }
        }
        __syncthreads();
    }

    const int rbase = bm + m0 + (lane >> 2);
    const int cbase = bn + n0 + 2 * (lane & 3);
    #pragma unroll
    for (int ni = 0; ni < 4; ni++) {
        int col = cbase + ni * 8;
        #pragma unroll
        for (int mi = 0; mi < 4; mi++) {
            int r0 = rbase + mi * 16;
            __half2 v0 = __floats2half2_rn(acc[mi][ni][0], acc[mi][ni][1]);
            __half2 v1 = __floats2half2_rn(acc[mi][ni][2], acc[mi][ni][3]);
            *(__half2*)(Ch + (long long)r0 * Nn + col)       = v0;
            *(__half2*)(Ch + (long long)(r0 + 8) * Nn + col) = v1;
        }
    }
}

// ============================================================================
// agemm: att @ h, both fp16 single -> 1 MMA/k16. relu.
// OUT: 0=fp32, 1=fp16 pair. Batched via blockIdx.z.
// ============================================================================
#define A_B_OFF 10240
#define A_STAGE 18944
static constexpr int ASMEM = 2 * A_STAGE;

template<int OUT>
__global__ __launch_bounds__(256)
void agemm(const __half* __restrict__ Ag, const __half* __restrict__ Bg,
           void* __restrict__ Co1, void* __restrict__ Co2)
{
    constexpr int BK = 32, K = NN, Nn = HH;
    extern __shared__ char dsm[];
    const uint32_t sb = smem_u32(dsm);

    const long long zA = (long long)blockIdx.z * NN * NN;
    const long long zB = (long long)blockIdx.z * NN * HH;
    const long long zC = (long long)blockIdx.z * NN * HH;
    const __half* A = Ag + zA;
    const __half* B = Bg + zB;

    const int bm = blockIdx.y * 128;
    const int bn = blockIdx.x * 128;
    const int tid  = threadIdx.x;
    const int lane = tid & 31;
    const int wid  = tid >> 5;
    const int m0 = (wid & 1) * 64, n0 = (wid >> 1) * 32;

    const uint32_t aoff = (uint32_t)(((m0 + (lane & 7) + ((lane >> 3) & 1) * 8) * APAD
                                     + (lane >> 4) * 8) * 2);
    const uint32_t boff = (uint32_t)((((lane & 7) + ((lane >> 3) & 1) * 8) * BPAD
                                     + n0 + (lane >> 4) * 8) * 2);

    float acc[4][4][4];
    #pragma unroll
    for (int mi = 0; mi < 4; mi++)
        #pragma unroll
        for (int ni = 0; ni < 4; ni++)
            #pragma unroll
            for (int r = 0; r < 4; r++) acc[mi][ni][r] = 0.f;

    const int nIter = K / BK;

    auto fill = [&](int stage, int k0) {
        uint32_t base = sb + stage * A_STAGE;
        #pragma unroll
        for (int l = 0; l < 2; l++) {
            int t = tid + (l << 8);
            int row = t >> 2, seg = t & 3;
            long long gsrc = (long long)(bm + row) * K + k0 + seg * 8;
            CP16(base + row * 80 + seg * 16, A + gsrc);
        }
        #pragma unroll
        for (int l = 0; l < 2; l++) {
            int t = tid + (l << 8);
            int row = t >> 4, seg = t & 15;
            long long gsrc = (long long)(k0 + row) * Nn + bn + seg * 8;
            CP16(base + A_B_OFF + row * 272 + seg * 16, B + gsrc);
        }
        CP_COMMIT();
    };

    fill(0, 0);

    for (int c = 0; c < nIter; ++c) {
        if (c + 1 < nIter) { fill((c + 1) & 1, (c + 1) * BK); CP_WAIT(1); }
        else               { CP_WAIT(0); }
        __syncthreads();

        const uint32_t base = sb + (c & 1) * A_STAGE;
        const uint32_t aB = base, bB = base + A_B_OFF;

        #pragma unroll
        for (int kk = 0; kk < BK; kk += 16) {
            uint32_t ah[4][4], bh[4][2];
            #pragma unroll
            for (int mi = 0; mi < 4; mi++) {
                uint32_t d = (uint32_t)((mi * 16 * APAD + kk) * 2);
                LDSM_X4(ah[mi][0], ah[mi][1], ah[mi][2], ah[mi][3], aB + aoff + d);
            }
            #pragma unroll
            for (int p = 0; p < 2; p++) {
                uint32_t d = (uint32_t)((kk * BPAD + p * 16) * 2);
                LDSM_X4T(bh[2 * p][0], bh[2 * p][1], bh[2 * p + 1][0], bh[2 * p + 1][1],
                         bB + boff + d);
            }
            #pragma unroll
            for (int mi = 0; mi < 4; mi++)
                #pragma unroll
                for (int ni = 0; ni < 4; ni++)
                    MMA_FP(acc[mi][ni], ah[mi], bh[ni]);
        }
        __syncthreads();
    }

    const int rbase = bm + m0 + (lane >> 2);
    const int cbase = bn + n0 + 2 * (lane & 3);
    #pragma unroll
    for (int ni = 0; ni < 4; ni++) {
        int col = cbase + ni * 8;
        #pragma unroll
        for (int mi = 0; mi < 4; mi++) {
            int r0 = rbase + mi * 16;
            float2 v0 = make_float2(fmaxf(acc[mi][ni][0], 0.f), fmaxf(acc[mi][ni][1], 0.f));
            float2 v1 = make_float2(fmaxf(acc[mi][ni][2], 0.f), fmaxf(acc[mi][ni][3], 0.f));
            long long o0 = zC + (long long)r0 * Nn + col;
            long long o1 = zC + (long long)(r0 + 8) * Nn + col;
            if (OUT == 0) {
                *(float2*)((float*)Co1 + o0) = v0;
                *(float2*)((float*)Co1 + o1) = v1;
            } else {
                uint32_t h0, l0, h1, l1;
                split_pair_h(v0.x, v0.y, h0, l0);
                split_pair_h(v1.x, v1.y, h1, l1);
                *(uint32_t*)((__half*)Co1 + o0) = h0;
                *(uint32_t*)((__half*)Co2 + o0) = l0;
                *(uint32_t*)((__half*)Co1 + o1) = h1;
                *(uint32_t*)((__half*)Co2 + o1) = l1;
            }
        }
    }
}

// ---------------- fused prep: nf/eW bf16 pairs, W0/W1 fp16 single ----------------
#define S0 (NB * NN * FIN / 4)
#define S1 (FIN * HH / 4)
#define S2 (HH * HH / 4)
__global__ __launch_bounds__(256)
void split_all(const float* __restrict__ nf, const float* __restrict__ eW,
               const float* __restrict__ W0, const float* __restrict__ W1,
               bf16* nfh, bf16* nfl, bf16* eWh, bf16* eWl,
               __half* W0f, __half* W1f)
{
    int i = blockIdx.x * 256 + threadIdx.x;
    if (i < S0 + S1) {
        const float* src; bf16 *ph, *pl; int off;
        if (i < S0) { src = nf; ph = nfh; pl = nfl; off = i; }
        else        { src = eW; ph = eWh; pl = eWl; off = i - S0; }
        float4 v = ((const float4*)src)[off];
        uint32_t h0, l0, h1, l1;
        split_pair(v.x, v.y, h0, l0);
        split_pair(v.z, v.w, h1, l1);
        *(uint2*)(ph + 4 * off) = make_uint2(h0, h1);
        *(uint2*)(pl + 4 * off) = make_uint2(l0, l1);
    } else if (i < S0 + S1 + 2 * S2) {
        const float* src; __half* pf; int off;
        if (i < S0 + S1 + S2) { src = W0; pf = W0f; off = i - S0 - S1; }
        else                  { src = W1; pf = W1f; off = i - S0 - S1 - S2; }
        float4 v = ((const float4*)src)[off];
        __half2 a = __floats2half2_rn(v.x, v.y);
        __half2 b = __floats2half2_rn(v.z, v.w);
        *(uint2*)(pf + 4 * off) = make_uint2(*(uint32_t*)&a, *(uint32_t*)&b);
    }
}

// ---------------- adjacency -> bitmask (ballot) ----------------
__global__ __launch_bounds__(256)
void adj2mask(const float* __restrict__ adj, uint32_t* __restrict__ mask)
{
    int lane = threadIdx.x & 31;
    int gw = blockIdx.x * 8 + (threadIdx.x >> 5);
    #pragma unroll
    for (int i = 0; i < 8; i++) {
        size_t w = (size_t)gw * 8 + i;
        float v = adj[w * 32 + lane];
        uint32_t b = __ballot_sync(0xFFFFFFFFu, v > 0.f);
        if (lane == 0) mask[w] = b;
    }
}

// ---------------- s1/s2 from fp16 single h ----------------
__global__ __launch_bounds__(256)
void s12_kernel(const __half* __restrict__ h,
                const float* __restrict__ a1, const float* __restrict__ a2,
                float* __restrict__ s1, float* __restrict__ s2)
{
    int row = blockIdx.x;
    int t = threadIdx.x;
    float v = __half2float(h[(size_t)row * HH + t]);
    float p1 = v * a1[t];
    float p2 = v * a2[t];
    p1 = warpSum(p1);
    p2 = warpSum(p2);
    __shared__ float r1[8], r2[8];
    if ((t & 31) == 0) { r1[t >> 5] = p1; r2[t >> 5] = p2; }
    __syncthreads();
    if (t == 0) {
        float t1 = 0.f, t2 = 0.f;
        #pragma unroll
        for (int w = 0; w < 8; w++) { t1 += r1[w]; t2 += r2[w]; }
        s1[row] = t1;
        s2[row] = t2;
    }
}

// ---------------- softmax row from bitmask -> fp16 attention ----------------
__global__ __launch_bounds__(256)
void stats_att_kernel(const uint32_t* __restrict__ mask, const float* __restrict__ s1,
                      const float* __restrict__ s2, __half* __restrict__ att)
{
    int bi = blockIdx.x;            // b*NN + i
    int b  = bi >> 10;
    const uint32_t* mrow = mask + (size_t)bi * (NN / 32);
    const float* s2b = s2 + b * NN;
    float s1i = s1[bi];
    int t = threadIdx.x;

    float e[4];
    float mx = -3.4e38f;
    #pragma unroll
    for (int k = 0; k < 4; k++) {
        int j = k * 256 + t;
        float sv = s1i + s2b[j];
        sv = sv >= 0.f ? sv : ALPHA * sv;
        bool on = (mrow[j >> 5] >> (j & 31)) & 1u;
        float ev = on ? sv : NEGV;
        e[k] = ev;
        mx = fmaxf(mx, ev);
    }
    __shared__ float redm[8], redz[8];
    float wm = warpMax(mx);
    if ((t & 31) == 0) redm[t >> 5] = wm;
    __syncthreads();
    float m = fmaxf(fmaxf(fmaxf(redm[0], redm[1]), fmaxf(redm[2], redm[3])),
                    fmaxf(fmaxf(redm[4], redm[5]), fmaxf(redm[6], redm[7])));

    float p[4];
    float zs = 0.f;
    #pragma unroll
    for (int k = 0; k < 4; k++) { p[k] = __expf(e[k] - m); zs += p[k]; }
    float ws = warpSum(zs);
    if ((t & 31) == 0) redz[t >> 5] = ws;
    __syncthreads();
    float z = redz[0] + redz[1] + redz[2] + redz[3] +
              redz[4] + redz[5] + redz[6] + redz[7];
    float rz = 1.f / z;

    size_t obase = (size_t)bi * NN;
    #pragma unroll
    for (int k = 0; k < 4; k++)
        att[obase + k * 256 + t] = __float2half_rn(p[k] * rz);
}

// ---------------- pooling partials ----------------
__global__ __launch_bounds__(256)
void pool_partial_kernel(const float* __restrict__ x, float* __restrict__ psum,
                         float* __restrict__ pmax)
{
    int b = blockIdx.y, c = blockIdx.x, hh = threadIdx.x;
    const float* xb = x + ((size_t)b * NN + c * 128) * HH + hh;
    float s = 0.f, mx = -3.4e38f;
    #pragma unroll 4
    for (int n = 0; n < 128; n++) {
        float v = xb[(size_t)n * HH];
        s += v;
        mx = fmaxf(mx, v);
    }
    psum[(b * 8 + c) * HH + hh] = s;
    pmax[(b * 8 + c) * HH + hh] = mx;
}

// ---------------- combine pooling + 2-layer MLP head ----------------
__global__ __launch_bounds__(256)
void pool_mlp_kernel(const float* __restrict__ psum, const float* __restrict__ pmax,
                     const float* __restrict__ W1, const float* __restrict__ b1,
                     const float* __restrict__ W2, const float* __restrict__ b2,
                     float* __restrict__ gout)
{
    int b = blockIdx.x, hh = threadIdx.x;
    __shared__ float g[HH], g1[HH];
    float s = 0.f, mx = -3.4e38f;
    #pragma unroll
    for (int c = 0; c < 8; c++) {
        s += psum[(b * 8 + c) * HH + hh];
        mx = fmaxf(mx, pmax[(b * 8 + c) * HH + hh]);
    }
    g[hh] = s * (1.f / (float)NN) + mx;
    __syncthreads();
    float acc = b1[hh];
    #pragma unroll 8
    for (int k = 0; k < HH; k++) acc = fmaf(g[k], W1[k * HH + hh], acc);
    g1[hh] = fmaxf(acc, 0.f);
    __syncthreads();
    float acc2 = b2[hh];
    #pragma unroll 8
    for (int k = 0; k < HH; k++) acc2 = fmaf(g1[k], W2[k * HH + hh], acc2);
    gout[b * HH + hh] = acc2;
}

// ---------------- host orchestration ----------------
extern "C" void kernel_launch(void* const* d_in, const int* in_sizes, int n_in,
                              void* d_out, int out_size)
{
    const float* nf   = (const float*)d_in[0];
    const float* adj  = (const float*)d_in[1];
    const float* embW = (const float*)d_in[2];
    const float* embb = (const float*)d_in[3];
    const float* W0   = (const float*)d_in[4];
    const float* a10  = (const float*)d_in[5];
    const float* a20  = (const float*)d_in[6];
    const float* W1   = (const float*)d_in[7];
    const float* a11  = (const float*)d_in[8];
    const float* a21  = (const float*)d_in[9];
    const float* gW1  = (const float*)d_in[10];
    const float* gb1  = (const float*)d_in[11];
    const float* gW2  = (const float*)d_in[12];
    const float* gb2  = (const float*)d_in[13];
    float* out = (float*)d_out;

    bf16 *nfh, *nfl, *eWh, *eWl;
    __half *W0f, *W1f, *xh, *xl, *yh, *yl, *hp, *attp;
    uint32_t* maskp;
    float *s1b, *s2b, *psb, *pmb;
    cudaGetSymbolAddress((void**)&nfh, g_nfhi); cudaGetSymbolAddress((void**)&nfl, g_nflo);
    cudaGetSymbolAddress((void**)&eWh, g_eWhi); cudaGetSymbolAddress((void**)&eWl, g_eWlo);
    cudaGetSymbolAddress((void**)&W0f, g_W0f);  cudaGetSymbolAddress((void**)&W1f, g_W1f);
    cudaGetSymbolAddress((void**)&xh,  g_xhi);  cudaGetSymbolAddress((void**)&xl,  g_xlo);
    cudaGetSymbolAddress((void**)&yh,  g_yhi);  cudaGetSymbolAddress((void**)&yl,  g_ylo);
    cudaGetSymbolAddress((void**)&hp,  g_hh);
    cudaGetSymbolAddress((void**)&attp, g_att);
    cudaGetSymbolAddress((void**)&maskp, g_mask);
    cudaGetSymbolAddress((void**)&s1b, g_s1);   cudaGetSymbolAddress((void**)&s2b, g_s2);
    cudaGetSymbolAddress((void**)&psb, g_ps);   cudaGetSymbolAddress((void**)&pmb, g_pm);

    cudaFuncSetAttribute(bgemm,    cudaFuncAttributeMaxDynamicSharedMemorySize, GSMEM);
    cudaFuncSetAttribute(hgemm,    cudaFuncAttributeMaxDynamicSharedMemorySize, HSMEM);
    cudaFuncSetAttribute(agemm<1>, cudaFuncAttributeMaxDynamicSharedMemorySize, ASMEM);
    cudaFuncSetAttribute(agemm<0>, cudaFuncAttributeMaxDynamicSharedMemorySize, ASMEM);

    const int M = NB * NN;               // 16384
    float* xout = out;                           // [B,N,H] part of output
    float* gout = out + (out_size - NB * HH);    // [B,H]  part of output

    // ---- prep ----
    split_all<<<(S0 + S1 + 2 * S2 + 255) / 256, 256>>>(
        nf, embW, W0, W1, nfh, nfl, eWh, eWl, W0f, W1f);
    adj2mask<<<NB * NN * (NN / 32) / 64, 256>>>(adj, maskp);

    // 1) emb: x = nf @ emb_W + emb_b  -> fp16 pair
    bgemm<<<dim3(HH / 128, M / 128, 1), 256, GSMEM>>>(
        nfh, nfl, eWh, eWl, embb, xh, xl, M, FIN, HH);

    // ---- GAT layer 0 ----
    hgemm<<<dim3(HH / 128, M / 128, 1), 256, HSMEM>>>(xh, xl, W0f, hp, M, HH, HH);
    s12_kernel<<<M, 256>>>(hp, a10, a20, s1b, s2b);
    stats_att_kernel<<<M, 256>>>(maskp, s1b, s2b, attp);
    agemm<1><<<dim3(HH / 128, NN / 128, NB), 256, ASMEM>>>(attp, hp, yh, yl);

    // ---- GAT layer 1 ----
    hgemm<<<dim3(HH / 128, M / 128, 1), 256, HSMEM>>>(yh, yl, W1f, hp, M, HH, HH);
    s12_kernel<<<M, 256>>>(hp, a11, a21, s1b, s2b);
    stats_att_kernel<<<M, 256>>>(maskp, s1b, s2b, attp);
    agemm<0><<<dim3(HH / 128, NN / 128, NB), 256, ASMEM>>>(attp, hp, xout, nullptr);

    // ---- pooling + MLP head ----
    pool_partial_kernel<<<dim3(8, NB), 256>>>(xout, psb, pmb);
    pool_mlp_kernel<<<NB, 256>>>(psb, pmb, gW1, gb1, gW2, gb2, gout);
}